// round 4
// baseline (speedup 1.0000x reference)
#include <cuda_runtime.h>
#include <math.h>
#include <stdint.h>

#define T_STEPS 512
#define BATCH   1024
#define HID     64
#define G4      256
#define B_TILE  8
#define NT      512

__device__ float g_buf0[BATCH * T_STEPS * HID];   // layer0 -> layer1
__device__ float g_buf1[BATCH * T_STEPS * HID];   // layer1 -> layer2

__device__ __forceinline__ float sigf(float x) {
    return __fdividef(1.0f, 1.0f + __expf(-x));
}
__device__ __forceinline__ float tanh_fast(float x) {
    float t = fabsf(x);
    float e = __expf(-2.0f * t);
    float r = __fdividef(1.0f - e, 1.0f + e);
    return copysignf(r, x);
}
__device__ __forceinline__ uint64_t pack2(float lo, float hi) {
    uint64_t r; asm("mov.b64 %0, {%1, %2};" : "=l"(r) : "f"(lo), "f"(hi)); return r;
}
__device__ __forceinline__ void unpack2(uint64_t v, float& lo, float& hi) {
    asm("mov.b64 {%0, %1}, %2;" : "=f"(lo), "=f"(hi) : "l"(v));
}
// d += a * b, two packed fp32 lanes (Blackwell FFMA2)
__device__ __forceinline__ void ffma2(uint64_t& d, uint64_t a, uint64_t b) {
    asm("fma.rn.f32x2 %0, %1, %2, %0;" : "+l"(d) : "l"(a), "l"(b));
}

// One CTA = 8 batch elements, 512 threads (16 warps).
// GEMM phase: thread = (gate column c = tid&255, K-half kh = tid>>8).
//   Weights for (c, kh) live in registers as packed k-pairs. Activations are
//   broadcast-read from smem xh (padded rows: 10 u64 per k2, data in first 8).
//   Accumulator lanes = (even-k partial, odd-k partial).
// Staging: gs[b][kh][c] float — each thread writes 8 partial gate sums.
// Epilogue phase: thread = (unit u = tid&63, batch b = tid>>6); sums the two
//   K-half partials, adds bias, activations, updates c-state, writes h.
template <int IN_W, bool LAST>
__global__ void __launch_bounds__(NT, 1)
lstm_layer(const float* __restrict__ x,     // [B][T][IN_W]
           const float* __restrict__ w_ih,  // [256][IN_W]
           const float* __restrict__ w_hh,  // [256][64]
           const float* __restrict__ b_ih,
           const float* __restrict__ b_hh,
           float* __restrict__ y,           // [B][T][64], or out[B][2] if LAST
           const float* __restrict__ fc1_w, const float* __restrict__ fc1_b,
           const float* __restrict__ fc3_w, const float* __restrict__ fc3_b,
           const float* __restrict__ fc2_w, const float* __restrict__ fc2_b)
{
    constexpr int K   = IN_W + HID;
    constexpr int K2  = K / 2;            // packed k-pairs
    constexpr int K2A = (K2 + 1) / 2;     // per-thread k2 count (first half)
    constexpr int K2P = 2 * K2A;          // padded k2 rows in xh
    constexpr int R64 = 10;               // u64 per xh row (8 data + 2 pad)

    extern __shared__ uint64_t smem[];
    uint64_t* xh   = smem;                          // [K2P][R64]
    float*    gsf  = (float*)(xh + K2P * R64);      // [8][2][256] = 4096 floats
    float*    head = gsf + 4096;                    // LAST only

    const int tid = threadIdx.x;
    const int b0  = blockIdx.x * B_TILE;

    // ---- GEMM-role identity ----
    const int c  = tid & 255;            // gate column = u*4 + gate
    const int kh = tid >> 8;             // K-half
    const int u  = c >> 2;
    const int gt = c & 3;
    const int r  = gt * HID + u;         // original gate-major row

    // ---- weights -> registers (one time) ----
    uint64_t w2[K2A];
#pragma unroll
    for (int i = 0; i < K2A; i++) {
        int k2g = kh * K2A + i;
        float w0 = 0.f, w1 = 0.f;
        if (k2g < K2) {
            int k = 2 * k2g;
            if (k < IN_W) { w0 = w_ih[r * IN_W + k];         w1 = w_ih[r * IN_W + k + 1]; }
            else          { w0 = w_hh[r * HID + (k - IN_W)]; w1 = w_hh[r * HID + (k - IN_W) + 1]; }
        }
        w2[i] = pack2(w0, w1);
    }

    // ---- epilogue-role identity + bias ----
    const int u_e = tid & 63;
    const int b_e = tid >> 6;
    float4 bias;
    bias.x = b_ih[0 * HID + u_e] + b_hh[0 * HID + u_e];
    bias.y = b_ih[1 * HID + u_e] + b_hh[1 * HID + u_e];
    bias.z = b_ih[2 * HID + u_e] + b_hh[2 * HID + u_e];
    bias.w = b_ih[3 * HID + u_e] + b_hh[3 * HID + u_e];

    // ---- init: zero xh (incl. pad rows), load x(0) ----
    for (int i = tid; i < K2P * R64; i += NT) xh[i] = 0ull;
    __syncthreads();
    if (IN_W == 64) {
        if (tid < 256) {
            int b = tid >> 5, l = tid & 31;
            float2 v = *(const float2*)(x + ((size_t)(b0 + b) * T_STEPS + 0) * IN_W + 2 * l);
            xh[l * R64 + b] = pack2(v.x, v.y);
        }
    } else {
        if (tid < (IN_W / 2) * 8) {
            int k2 = tid >> 3, b = tid & 7;
            float2 v = *(const float2*)(x + ((size_t)(b0 + b) * T_STEPS + 0) * IN_W + 2 * k2);
            xh[k2 * R64 + b] = pack2(v.x, v.y);
        }
    }
    __syncthreads();

    const ulonglong2* XH2 = (const ulonglong2*)xh + (size_t)kh * K2A * (R64 / 2);
    float c_state = 0.0f;

    for (int t = 0; t < T_STEPS; t++) {
        // prefetch x(t+1) into registers (hidden under the k-loop)
        float2 xpre = make_float2(0.f, 0.f);
        if (t + 1 < T_STEPS) {
            if (IN_W == 64) {
                if (tid < 256) {
                    int b = tid >> 5, l = tid & 31;
                    xpre = *(const float2*)(x + ((size_t)(b0 + b) * T_STEPS + (t + 1)) * IN_W + 2 * l);
                }
            } else if (tid < (IN_W / 2) * 8) {
                int k2 = tid >> 3, b = tid & 7;
                xpre = *(const float2*)(x + ((size_t)(b0 + b) * T_STEPS + (t + 1)) * IN_W + 2 * k2);
            }
        }

        // ---- gate GEMM: this thread's column, its K-half, 8 batches ----
        uint64_t acc[8];
#pragma unroll
        for (int j = 0; j < 8; j++) acc[j] = 0ull;
#pragma unroll
        for (int i = 0; i < K2A; i++) {
            ulonglong2 a0 = XH2[i * (R64 / 2) + 0];   // batches 0,1
            ulonglong2 a1 = XH2[i * (R64 / 2) + 1];   // batches 2,3
            ulonglong2 a2 = XH2[i * (R64 / 2) + 2];   // batches 4,5
            ulonglong2 a3 = XH2[i * (R64 / 2) + 3];   // batches 6,7
            uint64_t w = w2[i];
            ffma2(acc[0], a0.x, w); ffma2(acc[1], a0.y, w);
            ffma2(acc[2], a1.x, w); ffma2(acc[3], a1.y, w);
            ffma2(acc[4], a2.x, w); ffma2(acc[5], a2.y, w);
            ffma2(acc[6], a3.x, w); ffma2(acc[7], a3.y, w);
        }
        // horizontal add, stage partial gates: gs[b][kh][c]
#pragma unroll
        for (int b = 0; b < 8; b++) {
            float e, o;
            unpack2(acc[b], e, o);
            gsf[b * 512 + kh * 256 + c] = e + o;
        }
        __syncthreads();   // gates staged; all xh reads for step t done

        // ---- epilogue for (u_e, b_e) ----
        {
            const float* gb = gsf + b_e * 512 + 4 * u_e;
            float4 g0 = *(const float4*)gb;          // K-half 0
            float4 g1 = *(const float4*)(gb + 256);  // K-half 1
            float gi = bias.x + g0.x + g1.x;
            float gf = bias.y + g0.y + g1.y;
            float gg = bias.z + g0.z + g1.z;
            float go = bias.w + g0.w + g1.w;
            float iv = sigf(gi), fv = sigf(gf), gv = tanh_fast(gg), ov = sigf(go);
            c_state = fv * c_state + iv * gv;
            float h = ov * tanh_fast(c_state);

            // write h into xh at k = IN_W + u_e
            float* xf = (float*)xh;
            int k = IN_W + u_e;
            xf[(k >> 1) * (R64 * 2) + b_e * 2 + (k & 1)] = h;

            if (!LAST) {
                y[((size_t)(b0 + b_e) * T_STEPS + t) * HID + u_e] = h;
            } else if (t == T_STEPS - 1) {
                head[b_e * HID + u_e] = h;
            }
        }
        // store prefetched x(t+1)
        if (t + 1 < T_STEPS) {
            if (IN_W == 64) {
                if (tid < 256) {
                    int b = tid >> 5, l = tid & 31;
                    xh[l * R64 + b] = pack2(xpre.x, xpre.y);
                }
            } else if (tid < (IN_W / 2) * 8) {
                int k2 = tid >> 3, b = tid & 7;
                xh[k2 * R64 + b] = pack2(xpre.x, xpre.y);
            }
        }
        __syncthreads();   // xh(t+1) ready
    }

    // ---- fused MLP head (LAST layer only) ----
    if (LAST) {
        float* h_s = head;            // 512 floats  [8][64]
        float* z1  = head + 512;      // 1024        [8][128]
        float* z2  = head + 1536;     // 512         [8][64]
        float* wf1 = head + 2048;     // 8192        fc1_w staged
        float* wf3 = head + 10240;    // 8192        fc3_w staged
        for (int i = tid; i < 128 * 64; i += NT) wf1[i] = fc1_w[i];
        for (int i = tid; i < 64 * 128; i += NT) wf3[i] = fc3_w[i];
        __syncthreads();
        for (int v = tid; v < 8 * 128; v += NT) {
            int b = v >> 7, j = v & 127;
            float s = fc1_b[j];
#pragma unroll 8
            for (int k = 0; k < 64; k++) s += h_s[b * 64 + k] * wf1[j * 64 + k];
            z1[b * 128 + j] = fmaxf(s, 0.0f);
        }
        __syncthreads();
        for (int v = tid; v < 8 * 64; v += NT) {
            int b = v >> 6, j = v & 63;
            float s = fc3_b[j];
#pragma unroll 8
            for (int k = 0; k < 128; k++) s += z1[b * 128 + k] * wf3[j * 128 + k];
            z2[b * 64 + j] = fmaxf(s, 0.0f);
        }
        __syncthreads();
        if (tid < 16) {
            int b = tid >> 1, j = tid & 1;
            float s = fc2_b[j];
#pragma unroll
            for (int k = 0; k < 64; k++) s += z2[b * 64 + k] * fc2_w[j * 64 + k];
            y[(b0 + b) * 2 + j] = s;
        }
    }
}

extern "C" void kernel_launch(void* const* d_in, const int* in_sizes, int n_in,
                              void* d_out, int out_size)
{
    const float* x     = (const float*)d_in[0];
    const float* w_ih0 = (const float*)d_in[1];
    const float* w_hh0 = (const float*)d_in[2];
    const float* b_ih0 = (const float*)d_in[3];
    const float* b_hh0 = (const float*)d_in[4];
    const float* w_ih1 = (const float*)d_in[5];
    const float* w_hh1 = (const float*)d_in[6];
    const float* b_ih1 = (const float*)d_in[7];
    const float* b_hh1 = (const float*)d_in[8];
    const float* w_ih2 = (const float*)d_in[9];
    const float* w_hh2 = (const float*)d_in[10];
    const float* b_ih2 = (const float*)d_in[11];
    const float* b_hh2 = (const float*)d_in[12];
    const float* fc1_w = (const float*)d_in[13];
    const float* fc1_b = (const float*)d_in[14];
    const float* fc3_w = (const float*)d_in[15];
    const float* fc3_b = (const float*)d_in[16];
    const float* fc2_w = (const float*)d_in[17];
    const float* fc2_b = (const float*)d_in[18];
    float* out = (float*)d_out;

    float *buf0 = nullptr, *buf1 = nullptr;
    cudaGetSymbolAddress((void**)&buf0, g_buf0);
    cudaGetSymbolAddress((void**)&buf1, g_buf1);

    // smem: xh (K2P*10 u64) + gs (4096 f32) [+ head (18432 f32) for LAST]
    const int SM_L0 = 36 * 10 * 8 + 4096 * 4;            // 19264
    const int SM_L1 = 64 * 10 * 8 + 4096 * 4;            // 21504
    const int SM_L2 = SM_L1 + 18432 * 4;                 // 95232

    cudaFuncSetAttribute((const void*)lstm_layer<6,  false>,
                         cudaFuncAttributeMaxDynamicSharedMemorySize, SM_L0);
    cudaFuncSetAttribute((const void*)lstm_layer<64, false>,
                         cudaFuncAttributeMaxDynamicSharedMemorySize, SM_L1);
    cudaFuncSetAttribute((const void*)lstm_layer<64, true>,
                         cudaFuncAttributeMaxDynamicSharedMemorySize, SM_L2);

    const int GRID = BATCH / B_TILE;   // 128

    lstm_layer<6,  false><<<GRID, NT, SM_L0>>>(x,    w_ih0, w_hh0, b_ih0, b_hh0, buf0,
                                               nullptr, nullptr, nullptr, nullptr, nullptr, nullptr);
    lstm_layer<64, false><<<GRID, NT, SM_L1>>>(buf0, w_ih1, w_hh1, b_ih1, b_hh1, buf1,
                                               nullptr, nullptr, nullptr, nullptr, nullptr, nullptr);
    lstm_layer<64, true ><<<GRID, NT, SM_L2>>>(buf1, w_ih2, w_hh2, b_ih2, b_hh2, out,
                                               fc1_w, fc1_b, fc3_w, fc3_b, fc2_w, fc2_b);
}

// round 5
// speedup vs baseline: 1.3223x; 1.3223x over previous
#include <cuda_runtime.h>
#include <math.h>
#include <stdint.h>

#define T_STEPS 512
#define BATCH   1024
#define HID     64
#define B_TILE  8
#define NT      512

__device__ float g_buf0[BATCH * T_STEPS * HID];   // layer0 -> layer1
__device__ float g_buf1[BATCH * T_STEPS * HID];   // layer1 -> layer2

__device__ __forceinline__ float sigf(float x) {
    return __fdividef(1.0f, 1.0f + __expf(-x));
}
__device__ __forceinline__ float tanh_fast(float x) {
    float t = fabsf(x);
    float e = __expf(-2.0f * t);
    float r = __fdividef(1.0f - e, 1.0f + e);
    return copysignf(r, x);
}
__device__ __forceinline__ uint64_t pack2(float lo, float hi) {
    uint64_t r; asm("mov.b64 %0, {%1, %2};" : "=l"(r) : "f"(lo), "f"(hi)); return r;
}
__device__ __forceinline__ void unpack2(uint64_t v, float& lo, float& hi) {
    asm("mov.b64 {%0, %1}, %2;" : "=f"(lo), "=f"(hi) : "l"(v));
}
// d += a * b, two packed fp32 lanes (Blackwell FFMA2)
__device__ __forceinline__ void ffma2(uint64_t& d, uint64_t a, uint64_t b) {
    asm("fma.rn.f32x2 %0, %1, %2, %0;" : "+l"(d) : "l"(a), "l"(b));
}

// One CTA = 8 batch elements, 512 threads (16 warps).
// GEMM: thread = (column-pair cp = tid&127, K-quarter kq = tid>>7).
//   Columns c0=2cp, c1=2cp+1 (c = unit*4+gate; cp pairs gates (i,f) or (g,o)
//   of unit cp>>1). Weights for both columns, this thread's K/4 range, live in
//   registers as packed k-pairs. Activations broadcast-read from smem xh
//   (padded rows: 10 u64 per k2). acc lanes = (even-k, odd-k partials).
// Staging: gs[b][kq][cp] = float2(sum_c0, sum_c1).
// Epilogue: thread = (unit u=tid&63, batch b=tid>>6): one float4 per quarter,
//   sum 4 quarters + bias -> gates -> c/h update.
template <int IN_W, bool LAST>
__global__ void __launch_bounds__(NT, 1)
lstm_layer(const float* __restrict__ x,     // [B][T][IN_W]
           const float* __restrict__ w_ih,  // [256][IN_W]
           const float* __restrict__ w_hh,  // [256][64]
           const float* __restrict__ b_ih,
           const float* __restrict__ b_hh,
           float* __restrict__ y,           // [B][T][64], or out[B][2] if LAST
           const float* __restrict__ fc1_w, const float* __restrict__ fc1_b,
           const float* __restrict__ fc3_w, const float* __restrict__ fc3_b,
           const float* __restrict__ fc2_w, const float* __restrict__ fc2_b)
{
    constexpr int K   = IN_W + HID;
    constexpr int K2  = K / 2;             // packed k-pairs (35 or 64)
    constexpr int K2T = (K2 + 3) / 4;      // per-thread k2 count (9 or 16)
    constexpr int K2P = 4 * K2T;           // padded k2 rows (36 or 64)
    constexpr int R64 = 10;                // u64 per xh row (8 data + 2 pad)

    extern __shared__ uint64_t smem[];
    uint64_t* xh   = smem;                          // [K2P][R64]
    float2*   gs   = (float2*)(xh + K2P * R64);     // [8][4][128] float2 = 32KB
    float*    head = (float*)(gs + 8 * 4 * 128);    // LAST only

    const int tid = threadIdx.x;
    const int b0  = blockIdx.x * B_TILE;

    // ---- GEMM-role identity ----
    const int cp = tid & 127;
    const int kq = tid >> 7;
    const int ug = cp >> 1;
    const int gh = cp & 1;                  // 0:(i,f)  1:(g,o)
    const int r0 = (2 * gh)     * HID + ug; // gate-major rows
    const int r1 = (2 * gh + 1) * HID + ug;

    // ---- weights -> registers (one time) ----
    uint64_t wA[K2T], wB[K2T];
#pragma unroll
    for (int i = 0; i < K2T; i++) {
        int k2g = kq * K2T + i;
        float a0 = 0.f, a1 = 0.f, bq0 = 0.f, bq1 = 0.f;
        if (k2g < K2) {
            int k = 2 * k2g;
            if (k < IN_W) {
                a0  = w_ih[r0 * IN_W + k];  a1  = w_ih[r0 * IN_W + k + 1];
                bq0 = w_ih[r1 * IN_W + k];  bq1 = w_ih[r1 * IN_W + k + 1];
            } else {
                int kk = k - IN_W;
                a0  = w_hh[r0 * HID + kk];  a1  = w_hh[r0 * HID + kk + 1];
                bq0 = w_hh[r1 * HID + kk];  bq1 = w_hh[r1 * HID + kk + 1];
            }
        }
        wA[i] = pack2(a0, a1);
        wB[i] = pack2(bq0, bq1);
    }

    // ---- epilogue-role identity + bias ----
    const int u_e = tid & 63;
    const int b_e = tid >> 6;
    float4 bias;
    bias.x = b_ih[0 * HID + u_e] + b_hh[0 * HID + u_e];
    bias.y = b_ih[1 * HID + u_e] + b_hh[1 * HID + u_e];
    bias.z = b_ih[2 * HID + u_e] + b_hh[2 * HID + u_e];
    bias.w = b_ih[3 * HID + u_e] + b_hh[3 * HID + u_e];

    // ---- init: zero xh (incl. pad rows), then x(0) ----
    for (int i = tid; i < K2P * R64; i += NT) xh[i] = 0ull;
    __syncthreads();
    if (IN_W == 64) {
        if (tid < 256) {
            int b = tid >> 5, l = tid & 31;
            float2 v = *(const float2*)(x + ((size_t)(b0 + b) * T_STEPS + 0) * IN_W + 2 * l);
            xh[l * R64 + b] = pack2(v.x, v.y);
        }
    } else {
        if (tid < (IN_W / 2) * 8) {
            int k2 = tid >> 3, b = tid & 7;
            float2 v = *(const float2*)(x + ((size_t)(b0 + b) * T_STEPS + 0) * IN_W + 2 * k2);
            xh[k2 * R64 + b] = pack2(v.x, v.y);
        }
    }
    __syncthreads();

    const ulonglong2* XH2 =
        (const ulonglong2*)(xh + (size_t)kq * K2T * R64);   // this quarter's rows
    float c_state = 0.0f;

    for (int t = 0; t < T_STEPS; t++) {
        // prefetch x(t+1) (hidden under the k-loop)
        float2 xpre = make_float2(0.f, 0.f);
        if (t + 1 < T_STEPS) {
            if (IN_W == 64) {
                if (tid < 256) {
                    int b = tid >> 5, l = tid & 31;
                    xpre = *(const float2*)(x + ((size_t)(b0 + b) * T_STEPS + (t + 1)) * IN_W + 2 * l);
                }
            } else if (tid < (IN_W / 2) * 8) {
                int k2 = tid >> 3, b = tid & 7;
                xpre = *(const float2*)(x + ((size_t)(b0 + b) * T_STEPS + (t + 1)) * IN_W + 2 * k2);
            }
        }

        // ---- gate GEMM: 2 columns, this K-quarter, 8 batches ----
        uint64_t accA[8], accB[8];
#pragma unroll
        for (int j = 0; j < 8; j++) { accA[j] = 0ull; accB[j] = 0ull; }
#pragma unroll
        for (int i = 0; i < K2T; i++) {
            ulonglong2 a0 = XH2[i * (R64 / 2) + 0];   // batches 0,1
            ulonglong2 a1 = XH2[i * (R64 / 2) + 1];   // batches 2,3
            ulonglong2 a2 = XH2[i * (R64 / 2) + 2];   // batches 4,5
            ulonglong2 a3 = XH2[i * (R64 / 2) + 3];   // batches 6,7
            uint64_t wa = wA[i], wb = wB[i];
            ffma2(accA[0], a0.x, wa); ffma2(accB[0], a0.x, wb);
            ffma2(accA[1], a0.y, wa); ffma2(accB[1], a0.y, wb);
            ffma2(accA[2], a1.x, wa); ffma2(accB[2], a1.x, wb);
            ffma2(accA[3], a1.y, wa); ffma2(accB[3], a1.y, wb);
            ffma2(accA[4], a2.x, wa); ffma2(accB[4], a2.x, wb);
            ffma2(accA[5], a2.y, wa); ffma2(accB[5], a2.y, wb);
            ffma2(accA[6], a3.x, wa); ffma2(accB[6], a3.x, wb);
            ffma2(accA[7], a3.y, wa); ffma2(accB[7], a3.y, wb);
        }
        // stage: gs[b][kq][cp] = (colA, colB)
#pragma unroll
        for (int b = 0; b < 8; b++) {
            float eA, oA, eB, oB;
            unpack2(accA[b], eA, oA);
            unpack2(accB[b], eB, oB);
            gs[(b * 4 + kq) * 128 + cp] = make_float2(eA + oA, eB + oB);
        }
        __syncthreads();   // gates staged; all xh reads for step t done

        // ---- epilogue for (u_e, b_e) ----
        {
            const float4* g4 = (const float4*)gs;   // [8*4][64] float4
            float4 q0 = g4[(b_e * 4 + 0) * 64 + u_e];
            float4 q1 = g4[(b_e * 4 + 1) * 64 + u_e];
            float4 q2 = g4[(b_e * 4 + 2) * 64 + u_e];
            float4 q3 = g4[(b_e * 4 + 3) * 64 + u_e];
            float gi = bias.x + ((q0.x + q1.x) + (q2.x + q3.x));
            float gf = bias.y + ((q0.y + q1.y) + (q2.y + q3.y));
            float gg = bias.z + ((q0.z + q1.z) + (q2.z + q3.z));
            float go = bias.w + ((q0.w + q1.w) + (q2.w + q3.w));
            float iv = sigf(gi), fv = sigf(gf), gv = tanh_fast(gg), ov = sigf(go);
            c_state = fv * c_state + iv * gv;
            float h = ov * tanh_fast(c_state);

            // write h into xh at k = IN_W + u_e
            float* xf = (float*)xh;
            int k = IN_W + u_e;
            xf[(k >> 1) * (R64 * 2) + b_e * 2 + (k & 1)] = h;

            if (!LAST) {
                y[((size_t)(b0 + b_e) * T_STEPS + t) * HID + u_e] = h;
            } else if (t == T_STEPS - 1) {
                head[b_e * HID + u_e] = h;
            }
        }
        // store prefetched x(t+1)
        if (t + 1 < T_STEPS) {
            if (IN_W == 64) {
                if (tid < 256) {
                    int b = tid >> 5, l = tid & 31;
                    xh[l * R64 + b] = pack2(xpre.x, xpre.y);
                }
            } else if (tid < (IN_W / 2) * 8) {
                int k2 = tid >> 3, b = tid & 7;
                xh[k2 * R64 + b] = pack2(xpre.x, xpre.y);
            }
        }
        __syncthreads();   // xh(t+1) ready
    }

    // ---- fused MLP head (LAST layer only) ----
    if (LAST) {
        float* h_s = head;            // 512 floats  [8][64]
        float* z1  = head + 512;      // 1024        [8][128]
        float* z2  = head + 1536;     // 512         [8][64]
        float* wf1 = head + 2048;     // 8192        fc1_w staged
        float* wf3 = head + 10240;    // 8192        fc3_w staged
        for (int i = tid; i < 128 * 64; i += NT) wf1[i] = fc1_w[i];
        for (int i = tid; i < 64 * 128; i += NT) wf3[i] = fc3_w[i];
        __syncthreads();
        for (int v = tid; v < 8 * 128; v += NT) {
            int b = v >> 7, j = v & 127;
            float s = fc1_b[j];
#pragma unroll 8
            for (int k = 0; k < 64; k++) s += h_s[b * 64 + k] * wf1[j * 64 + k];
            z1[b * 128 + j] = fmaxf(s, 0.0f);
        }
        __syncthreads();
        for (int v = tid; v < 8 * 64; v += NT) {
            int b = v >> 6, j = v & 63;
            float s = fc3_b[j];
#pragma unroll 8
            for (int k = 0; k < 128; k++) s += z1[b * 128 + k] * wf3[j * 128 + k];
            z2[b * 64 + j] = fmaxf(s, 0.0f);
        }
        __syncthreads();
        if (tid < 16) {
            int b = tid >> 1, j = tid & 1;
            float s = fc2_b[j];
#pragma unroll
            for (int k = 0; k < 64; k++) s += z2[b * 64 + k] * fc2_w[j * 64 + k];
            y[(b0 + b) * 2 + j] = s;
        }
    }
}

extern "C" void kernel_launch(void* const* d_in, const int* in_sizes, int n_in,
                              void* d_out, int out_size)
{
    const float* x     = (const float*)d_in[0];
    const float* w_ih0 = (const float*)d_in[1];
    const float* w_hh0 = (const float*)d_in[2];
    const float* b_ih0 = (const float*)d_in[3];
    const float* b_hh0 = (const float*)d_in[4];
    const float* w_ih1 = (const float*)d_in[5];
    const float* w_hh1 = (const float*)d_in[6];
    const float* b_ih1 = (const float*)d_in[7];
    const float* b_hh1 = (const float*)d_in[8];
    const float* w_ih2 = (const float*)d_in[9];
    const float* w_hh2 = (const float*)d_in[10];
    const float* b_ih2 = (const float*)d_in[11];
    const float* b_hh2 = (const float*)d_in[12];
    const float* fc1_w = (const float*)d_in[13];
    const float* fc1_b = (const float*)d_in[14];
    const float* fc3_w = (const float*)d_in[15];
    const float* fc3_b = (const float*)d_in[16];
    const float* fc2_w = (const float*)d_in[17];
    const float* fc2_b = (const float*)d_in[18];
    float* out = (float*)d_out;

    float *buf0 = nullptr, *buf1 = nullptr;
    cudaGetSymbolAddress((void**)&buf0, g_buf0);
    cudaGetSymbolAddress((void**)&buf1, g_buf1);

    // smem: xh (K2P*10 u64) + gs (4096 float2 = 32768B) [+ head for LAST]
    const int SM_L0 = 36 * 10 * 8 + 32768;               // 35648
    const int SM_L1 = 64 * 10 * 8 + 32768;               // 37888
    const int SM_L2 = SM_L1 + 18432 * 4;                 // 111616

    cudaFuncSetAttribute((const void*)lstm_layer<6,  false>,
                         cudaFuncAttributeMaxDynamicSharedMemorySize, SM_L0);
    cudaFuncSetAttribute((const void*)lstm_layer<64, false>,
                         cudaFuncAttributeMaxDynamicSharedMemorySize, SM_L1);
    cudaFuncSetAttribute((const void*)lstm_layer<64, true>,
                         cudaFuncAttributeMaxDynamicSharedMemorySize, SM_L2);

    const int GRID = BATCH / B_TILE;   // 128

    lstm_layer<6,  false><<<GRID, NT, SM_L0>>>(x,    w_ih0, w_hh0, b_ih0, b_hh0, buf0,
                                               nullptr, nullptr, nullptr, nullptr, nullptr, nullptr);
    lstm_layer<64, false><<<GRID, NT, SM_L1>>>(buf0, w_ih1, w_hh1, b_ih1, b_hh1, buf1,
                                               nullptr, nullptr, nullptr, nullptr, nullptr, nullptr);
    lstm_layer<64, true ><<<GRID, NT, SM_L2>>>(buf1, w_ih2, w_hh2, b_ih2, b_hh2, out,
                                               fc1_w, fc1_b, fc3_w, fc3_b, fc2_w, fc2_b);
}